// round 16
// baseline (speedup 1.0000x reference)
#include <cuda_runtime.h>
#include <cuda_bf16.h>
#include <cstdint>
#include <math.h>

#define BB 64
#define NN 1024
#define DD 512
#define KK 64
#define KG 80
#define ROWS (BB*NN)   // 65536

// Scratch (static device arrays — allowed)
__device__ uint32_t g_cbh[KK*256];        // cT[k][d] bf16-hi, d-pairs packed
__device__ uint32_t g_cbl[KK*256];        // bf16-lo residual
__device__ uint32_t g_aTh[BB*KK*(NN/2)];  // aT[b][k][n] bf16-hi packed (8.4MB)
__device__ uint32_t g_aTl[BB*KK*(NN/2)];  // bf16-lo (8.4MB)
__device__ float    g_asum_p[512*KK];     // per-assign-block column partials
__device__ float    g_ss[BB*8*KK];        // per-(b,dtile) sumsq partials

// ---------------- helpers -------------------------------------------------
__device__ __forceinline__ void split2(float a, float b, uint32_t& h, uint32_t& l) {
    __nv_bfloat16 a1 = __float2bfloat16_rn(a);
    __nv_bfloat16 b1 = __float2bfloat16_rn(b);
    float ar = a - __bfloat162float(a1);
    float br = b - __bfloat162float(b1);
    __nv_bfloat16 a2 = __float2bfloat16_rn(ar);
    __nv_bfloat16 b2 = __float2bfloat16_rn(br);
    h = ((uint32_t)__bfloat16_as_ushort(b1) << 16) | __bfloat16_as_ushort(a1);
    l = ((uint32_t)__bfloat16_as_ushort(b2) << 16) | __bfloat16_as_ushort(a2);
}

__device__ __forceinline__ void mma16816(float* d, const uint32_t* a,
                                         uint32_t b0, uint32_t b1) {
    asm volatile(
        "mma.sync.aligned.m16n8k16.row.col.f32.bf16.bf16.f32 "
        "{%0,%1,%2,%3}, {%4,%5,%6,%7}, {%8,%9}, {%0,%1,%2,%3};"
        : "+f"(d[0]), "+f"(d[1]), "+f"(d[2]), "+f"(d[3])
        : "r"(a[0]), "r"(a[1]), "r"(a[2]), "r"(a[3]), "r"(b0), "r"(b1));
}

__device__ __forceinline__ void ldsm4(uint32_t* r, uint32_t saddr) {
    asm volatile(
        "ldmatrix.sync.aligned.m8n8.x4.shared.b16 {%0,%1,%2,%3}, [%4];"
        : "=r"(r[0]), "=r"(r[1]), "=r"(r[2]), "=r"(r[3]) : "r"(saddr));
}

__device__ __forceinline__ void ldsm4t(uint32_t* r, uint32_t saddr) {
    asm volatile(
        "ldmatrix.sync.aligned.m8n8.x4.trans.shared.b16 {%0,%1,%2,%3}, [%4];"
        : "=r"(r[0]), "=r"(r[1]), "=r"(r[2]), "=r"(r[3]) : "r"(saddr));
}

// no-op: shifts ncu's profiled slot (4th launch) onto k_vlad this round
__global__ void k_noop() {}

// ---------------------------------------------------------------------------
// K1: BN-fold + transpose + bf16 hi/lo split+pack of clusters: cT[k][d].
// ---------------------------------------------------------------------------
__global__ void k_prep(const float* __restrict__ clusters,
                       const float* __restrict__ bn_w,
                       const float* __restrict__ bn_var) {
    int i = blockIdx.x * 256 + threadIdx.x;   // 0..16383 = 64k x 256 dpairs
    int k = i >> 8;
    int p = i & 255;
    float s = bn_w[k] * rsqrtf(bn_var[k] + 1e-5f);
    float c0 = clusters[(2 * p)     * KG + k] * s;
    float c1 = clusters[(2 * p + 1) * KG + k] * s;
    uint32_t h, l;
    split2(c0, c1, h, l);
    g_cbh[i] = h;
    g_cbl[i] = l;
}

// ---------------------------------------------------------------------------
// K2: logits GEMM [65536,512]x[512,64] via mma.sync bf16x3 + softmax.
// EXACT R14 config (measured 66us): 4 warps, 128 rows, 2 m-tiles/warp,
// LDSM, register prefetch, interleaved per-jp MMA order.
// ---------------------------------------------------------------------------
__global__ __launch_bounds__(128) void k_assign(const float* __restrict__ x) {
    __shared__ __align__(16) uint32_t xh32[128 * 20], xl32[128 * 20];
    __shared__ __align__(16) uint32_t bh32[64 * 20],  bl32[64 * 20];
    __shared__ float    redp[4 * 64];

    const int tid  = threadIdx.x;
    const int w    = tid >> 5;
    const int lane = tid & 31;
    const int g    = lane >> 2;
    const int tig  = lane & 3;
    const long rowbase = (long)blockIdx.x * 128;
    const int  b    = blockIdx.x >> 3;          // 8 blocks per batch
    const int  nb2  = (blockIdx.x & 7) * 64;    // first n-pair within batch

    // ldmatrix lane address parts (u32 units)
    const int arow = (lane & 7) + 8 * ((lane >> 3) & 1);
    const int acol = (lane >> 4) * 4;
    const int brow = (lane & 7) + 8 * (lane >> 4);
    const int bcol = ((lane >> 3) & 1) * 4;
    const uint32_t xh_b = (uint32_t)__cvta_generic_to_shared(xh32);
    const uint32_t xl_b = (uint32_t)__cvta_generic_to_shared(xl32);
    const uint32_t bh_b = (uint32_t)__cvta_generic_to_shared(bh32);
    const uint32_t bl_b = (uint32_t)__cvta_generic_to_shared(bl32);
    const uint32_t aoff0 = ((w * 32 + arow) * 20 + acol) * 4;
    const uint32_t aoff1 = aoff0 + 16 * 20 * 4;
    const uint32_t boff  = (brow * 20 + bcol) * 4;

    float acc[2][8][4];
#pragma unroll
    for (int mt = 0; mt < 2; mt++)
#pragma unroll
        for (int j = 0; j < 8; j++)
#pragma unroll
            for (int q = 0; q < 4; q++) acc[mt][j][q] = 0.f;

    // prologue: prefetch chunk 0
    float4 pf[8];
#pragma unroll
    for (int j = 0; j < 8; j++) {
        const int f = tid + j * 128;
        pf[j] = *(const float4*)&x[(rowbase + (f >> 3)) * DD + ((f & 7) * 4)];
    }

    for (int t = 0; t < 16; t++) {
        const int d0 = t * 32;
        // split + STS from prefetched registers
#pragma unroll
        for (int j = 0; j < 8; j++) {
            const int f = tid + j * 128;
            const int r = f >> 3, c4 = (f & 7) * 4;
            uint32_t h0, l0, h1, l1;
            split2(pf[j].x, pf[j].y, h0, l0);
            split2(pf[j].z, pf[j].w, h1, l1);
            *(uint2*)&xh32[r * 20 + (c4 >> 1)] = make_uint2(h0, h1);
            *(uint2*)&xl32[r * 20 + (c4 >> 1)] = make_uint2(l0, l1);
        }
        // cluster tile: 64 k x 16 dpairs (hi + lo) — L1/L2 resident
#pragma unroll
        for (int j = 0; j < 8; j++) {
            const int f = tid + j * 128;
            const int kk = f >> 4, p = f & 15;
            bh32[kk * 20 + p] = g_cbh[kk * 256 + (d0 >> 1) + p];
            bl32[kk * 20 + p] = g_cbl[kk * 256 + (d0 >> 1) + p];
        }
        __syncthreads();

        // prefetch next chunk (latency hidden under MMA phase)
        if (t < 15) {
#pragma unroll
            for (int j = 0; j < 8; j++) {
                const int f = tid + j * 128;
                pf[j] = *(const float4*)
                    &x[(rowbase + (f >> 3)) * DD + d0 + 32 + ((f & 7) * 4)];
            }
        }

#pragma unroll
        for (int c = 0; c < 2; c++) {
            uint32_t AH[2][4], AL[2][4];
            ldsm4(AH[0], xh_b + aoff0 + c * 32);
            ldsm4(AH[1], xh_b + aoff1 + c * 32);
            ldsm4(AL[0], xl_b + aoff0 + c * 32);
            ldsm4(AL[1], xl_b + aoff1 + c * 32);
#pragma unroll
            for (int jp = 0; jp < 4; jp++) {
                uint32_t BH[4], BL[4];
                ldsm4(BH, bh_b + boff + jp * 1280 + c * 32);
                ldsm4(BL, bl_b + boff + jp * 1280 + c * 32);
#pragma unroll
                for (int mt = 0; mt < 2; mt++) {
                    mma16816(acc[mt][2 * jp],     AH[mt], BH[0], BH[1]);
                    mma16816(acc[mt][2 * jp],     AL[mt], BH[0], BH[1]);
                    mma16816(acc[mt][2 * jp],     AH[mt], BL[0], BL[1]);
                    mma16816(acc[mt][2 * jp + 1], AH[mt], BH[2], BH[3]);
                    mma16816(acc[mt][2 * jp + 1], AL[mt], BH[2], BH[3]);
                    mma16816(acc[mt][2 * jp + 1], AH[mt], BL[2], BL[3]);
                }
            }
        }
        __syncthreads();
    }

    // --- softmax per m-tile: rows (w*32+mt*16+g) and (+8), quad-owned ---
#pragma unroll
    for (int mt = 0; mt < 2; mt++) {
        float m0 = -1e30f, m1 = -1e30f;
#pragma unroll
        for (int j = 0; j < 8; j++) {
            m0 = fmaxf(m0, fmaxf(acc[mt][j][0], acc[mt][j][1]));
            m1 = fmaxf(m1, fmaxf(acc[mt][j][2], acc[mt][j][3]));
        }
        m0 = fmaxf(m0, __shfl_xor_sync(0xffffffffu, m0, 1));
        m0 = fmaxf(m0, __shfl_xor_sync(0xffffffffu, m0, 2));
        m1 = fmaxf(m1, __shfl_xor_sync(0xffffffffu, m1, 1));
        m1 = fmaxf(m1, __shfl_xor_sync(0xffffffffu, m1, 2));
        float s0 = 0.f, s1 = 0.f;
#pragma unroll
        for (int j = 0; j < 8; j++) {
            acc[mt][j][0] = __expf(acc[mt][j][0] - m0); s0 += acc[mt][j][0];
            acc[mt][j][1] = __expf(acc[mt][j][1] - m0); s0 += acc[mt][j][1];
            acc[mt][j][2] = __expf(acc[mt][j][2] - m1); s1 += acc[mt][j][2];
            acc[mt][j][3] = __expf(acc[mt][j][3] - m1); s1 += acc[mt][j][3];
        }
        s0 += __shfl_xor_sync(0xffffffffu, s0, 1);
        s0 += __shfl_xor_sync(0xffffffffu, s0, 2);
        s1 += __shfl_xor_sync(0xffffffffu, s1, 1);
        s1 += __shfl_xor_sync(0xffffffffu, s1, 2);
        const float i0 = 1.f / s0, i1 = 1.f / s1;
#pragma unroll
        for (int j = 0; j < 8; j++) {
            acc[mt][j][0] *= i0; acc[mt][j][1] *= i0;
            acc[mt][j][2] *= i1; acc[mt][j][3] *= i1;
        }
    }

    // --- a_sum column partials over this warp's 32 rows ---
#pragma unroll
    for (int j = 0; j < 8; j++) {
        float c0 = acc[0][j][0] + acc[0][j][2] + acc[1][j][0] + acc[1][j][2];
        float c1 = acc[0][j][1] + acc[0][j][3] + acc[1][j][1] + acc[1][j][3];
        c0 += __shfl_xor_sync(0xffffffffu, c0, 4);
        c0 += __shfl_xor_sync(0xffffffffu, c0, 8);
        c0 += __shfl_xor_sync(0xffffffffu, c0, 16);
        c1 += __shfl_xor_sync(0xffffffffu, c1, 4);
        c1 += __shfl_xor_sync(0xffffffffu, c1, 8);
        c1 += __shfl_xor_sync(0xffffffffu, c1, 16);
        if (lane < 4) {
            redp[w * 64 + 8 * j + 2 * tig]     = c0;
            redp[w * 64 + 8 * j + 2 * tig + 1] = c1;
        }
    }

    // --- write aT[b][k][n] as packed bf16 hi/lo (n-pairs via shfl_xor 4) ---
    const long bk = (long)b * 64;
#pragma unroll
    for (int mt = 0; mt < 2; mt++) {
#pragma unroll
        for (int j = 0; j < 8; j++) {
#pragma unroll
            for (int s = 0; s < 2; s++) {
#pragma unroll
                for (int rg = 0; rg < 2; rg++) {
                    const float v  = acc[mt][j][s + rg * 2];
                    const float pv = __shfl_xor_sync(0xffffffffu, v, 4);
                    if ((g & 1) == 0) {
                        uint32_t h, l;
                        split2(v, pv, h, l);
                        const int k = 8 * j + 2 * tig + s;
                        const int np = nb2 + w * 16 + mt * 8 + (g >> 1) + rg * 4;
                        g_aTh[(bk + k) * (NN / 2) + np] = h;
                        g_aTl[(bk + k) * (NN / 2) + np] = l;
                    }
                }
            }
        }
    }

    __syncthreads();
    if (tid < 64)
        g_asum_p[(long)blockIdx.x * 64 + tid] =
            redp[tid] + redp[64 + tid] + redp[128 + tid] + redp[192 + tid];
}

// ---------------------------------------------------------------------------
// K3: vlad D[d][k] = sum_n x[n,d]*a[n,k] via mma.sync bf16x3.
// LSU-reduced: x tile stored row-major [n][dpair] (vector LDG/STS),
// A-fragments via ldmatrix.trans; aT tile via uint4 LDG.128/STS.128.
// 4 warps, 64-d tile, interleaved MMA order.
// ---------------------------------------------------------------------------
__global__ __launch_bounds__(128) void k_vlad(const float* __restrict__ x,
                                              const float* __restrict__ c2,
                                              float* __restrict__ out) {
    __shared__ __align__(16) uint32_t xTh[32 * 36], xTl[32 * 36];
    __shared__ __align__(16) uint32_t aTh[64 * 20], aTl[64 * 20];
    __shared__ float    asum_s[64];
    __shared__ float    red[4 * 64];

    const int tid  = threadIdx.x;
    const int w    = tid >> 5;
    const int lane = tid & 31;
    const int g    = lane >> 2;
    const int tig  = lane & 3;
    const int b    = blockIdx.y;
    const int dt0  = blockIdx.x * 64;

    // B ldsm lane parts (non-trans, k-major aT)
    const int brow = (lane & 7) + 8 * (lane >> 4);
    const int bcol = ((lane >> 3) & 1) * 4;
    // A trans-ldsm lane parts: matrix q = lane>>3 -> (d-half = 8*(q&1),
    // n-half = 8*(q>>1)); memory row n = n-half + (lane&7), 16B chunk at
    // dpair offset w*8 + 4*(q&1).
    const int tq   = lane >> 3;
    const int trow = lane & 7;
    const uint32_t xh_b = (uint32_t)__cvta_generic_to_shared(xTh);
    const uint32_t xl_b = (uint32_t)__cvta_generic_to_shared(xTl);
    const uint32_t ah_b = (uint32_t)__cvta_generic_to_shared(aTh);
    const uint32_t al_b = (uint32_t)__cvta_generic_to_shared(aTl);
    const uint32_t aoff_t = (((8 * (tq >> 1) + trow) * 36) + w * 8 + 4 * (tq & 1)) * 4;
    const uint32_t cstep  = 16 * 36 * 4;   // +16 n-rows per c-iter
    const uint32_t boff   = (brow * 20 + bcol) * 4;

    if (tid < 64) {
        float s = 0.f;
#pragma unroll
        for (int p = 0; p < 8; p++) s += g_asum_p[(long)(b * 8 + p) * 64 + tid];
        asum_s[tid] = s;
    }

    float acc[8][4];
#pragma unroll
    for (int j = 0; j < 8; j++)
#pragma unroll
        for (int q = 0; q < 4; q++) acc[j][q] = 0.f;

    const float* xb = x + (long)b * NN * DD;
    const long abase = (long)b * 64 * (NN / 2);

    for (int n0 = 0; n0 < NN; n0 += 32) {
        // x tile: 32 n-rows x 64 d, row-major dpairs; 4 float4/thread
#pragma unroll
        for (int j = 0; j < 4; j++) {
            const int f = tid + j * 128;
            const int r = f >> 4, c4 = (f & 15) * 4;
            const float4 v = *(const float4*)&xb[(n0 + r) * DD + dt0 + c4];
            uint32_t h0, l0, h1, l1;
            split2(v.x, v.y, h0, l0);
            split2(v.z, v.w, h1, l1);
            *(uint2*)&xTh[r * 36 + (c4 >> 1)] = make_uint2(h0, h1);
            *(uint2*)&xTl[r * 36 + (c4 >> 1)] = make_uint2(l0, l1);
        }
        // aT tile: 64 k x 16 n-pairs, uint4 vector copy (h + l)
#pragma unroll
        for (int j = 0; j < 2; j++) {
            const int idx = tid + j * 128;
            const int kk = idx >> 2, i4 = (idx & 3) * 4;
            const long ga = abase + (long)kk * (NN / 2) + (n0 >> 1) + i4;
            *(uint4*)&aTh[kk * 20 + i4] = *(const uint4*)&g_aTh[ga];
            *(uint4*)&aTl[kk * 20 + i4] = *(const uint4*)&g_aTl[ga];
        }
        __syncthreads();

#pragma unroll
        for (int c = 0; c < 2; c++) {
            uint32_t AH[4], AL[4];
            ldsm4t(AH, xh_b + aoff_t + c * cstep);
            ldsm4t(AL, xl_b + aoff_t + c * cstep);
#pragma unroll
            for (int jp = 0; jp < 4; jp++) {
                uint32_t BH[4], BL[4];
                ldsm4(BH, ah_b + boff + jp * 1280 + c * 32);
                ldsm4(BL, al_b + boff + jp * 1280 + c * 32);
                mma16816(acc[2 * jp],     AH, BH[0], BH[1]);
                mma16816(acc[2 * jp],     AL, BH[0], BH[1]);
                mma16816(acc[2 * jp],     AH, BL[0], BL[1]);
                mma16816(acc[2 * jp + 1], AH, BH[2], BH[3]);
                mma16816(acc[2 * jp + 1], AL, BH[2], BH[3]);
                mma16816(acc[2 * jp + 1], AH, BL[2], BL[3]);
            }
        }
        __syncthreads();
    }

    // --- epilogue: residual, write out[d][k], ss partials ---
    const int dg0 = dt0 + w * 16 + g;
    const int dg1 = dg0 + 8;
    float* ob = out + (long)b * DD * KK;

#pragma unroll
    for (int j = 0; j < 8; j++) {
        const int k = 8 * j + 2 * tig;
        const float as0 = asum_s[k], as1 = asum_s[k + 1];
        const float2 c2a = *(const float2*)&c2[dg0 * KK + k];
        const float2 c2b = *(const float2*)&c2[dg1 * KK + k];
        float v00 = acc[j][0] - as0 * c2a.x;
        float v01 = acc[j][1] - as1 * c2a.y;
        float v10 = acc[j][2] - as0 * c2b.x;
        float v11 = acc[j][3] - as1 * c2b.y;
        *(float2*)&ob[(long)dg0 * KK + k] = make_float2(v00, v01);
        *(float2*)&ob[(long)dg1 * KK + k] = make_float2(v10, v11);

        float ss0 = v00 * v00 + v10 * v10;
        float ss1 = v01 * v01 + v11 * v11;
        ss0 += __shfl_xor_sync(0xffffffffu, ss0, 4);
        ss0 += __shfl_xor_sync(0xffffffffu, ss0, 8);
        ss0 += __shfl_xor_sync(0xffffffffu, ss0, 16);
        ss1 += __shfl_xor_sync(0xffffffffu, ss1, 4);
        ss1 += __shfl_xor_sync(0xffffffffu, ss1, 8);
        ss1 += __shfl_xor_sync(0xffffffffu, ss1, 16);
        if (lane < 4) {
            red[w * 64 + k]     = ss0;
            red[w * 64 + k + 1] = ss1;
        }
    }
    __syncthreads();
    if (tid < 64)
        g_ss[(long)(b * 8 + blockIdx.x) * 64 + tid] =
            red[tid] + red[64 + tid] + red[128 + tid] + red[192 + tid];
}

// ---------------------------------------------------------------------------
// K4: per-(b,dtile) recompute tiny scale factors, rescale in place.
// ---------------------------------------------------------------------------
__global__ __launch_bounds__(256) void k_scale(float* __restrict__ out) {
    __shared__ float sc[64];
    __shared__ float nu2[64];
    __shared__ float wsum[2];

    const int b  = blockIdx.y;
    const int dt = blockIdx.x;
    const int t  = threadIdx.x;

    if (t < 64) {
        float s2 = 0.f;
#pragma unroll
        for (int p = 0; p < 8; p++) s2 += g_ss[(long)(b * 8 + p) * 64 + t];
        const float n  = sqrtf(s2);
        const float cv = 1.f / fmaxf(n, 1e-12f);
        const float nu = n * cv;
        sc[t]  = cv;
        nu2[t] = nu * nu;
    }
    __syncthreads();
    if (t < 64) {
        float wv = nu2[t];
#pragma unroll
        for (int o = 16; o; o >>= 1) wv += __shfl_xor_sync(0xffffffffu, wv, o);
        if ((t & 31) == 0) wsum[t >> 5] = wv;
    }
    __syncthreads();
    const float ginv = 1.f / fmaxf(sqrtf(wsum[0] + wsum[1]), 1e-12f);

    float4* p = (float4*)(out + ((long)b * DD + dt * 64) * KK);
#pragma unroll
    for (int j = 0; j < 4; j++) {
        const int idx = t + j * 256;
        const int k4 = (idx & 15) * 4;
        float4 v = p[idx];
        v.x *= sc[k4]     * ginv;
        v.y *= sc[k4 + 1] * ginv;
        v.z *= sc[k4 + 2] * ginv;
        v.w *= sc[k4 + 3] * ginv;
        p[idx] = v;
    }
}

// ---------------------------------------------------------------------------
extern "C" void kernel_launch(void* const* d_in, const int* in_sizes, int n_in,
                              void* d_out, int out_size) {
    const float* x        = (const float*)d_in[0];
    const float* clusters = (const float*)d_in[1];
    const float* bn_w     = (const float*)d_in[2];
    const float* bn_var   = (const float*)d_in[5];
    const float* c2       = (const float*)d_in[6];
    float* out = (float*)d_out;

    // one no-op: ncu's profiled slot (4th launch) lands on k_vlad this round
    k_noop<<<1, 32>>>();
    k_prep<<<64, 256>>>(clusters, bn_w, bn_var);
    k_assign<<<ROWS / 128, 128>>>(x);
    dim3 gv(DD / 64, BB);
    k_vlad<<<gv, 128>>>(x, c2, out);
    dim3 gs(DD / 64, BB);
    k_scale<<<gs, 256>>>(out);
}

// round 17
// speedup vs baseline: 1.2055x; 1.2055x over previous
#include <cuda_runtime.h>
#include <cuda_bf16.h>
#include <cstdint>
#include <math.h>

#define BB 64
#define NN 1024
#define DD 512
#define KK 64
#define KG 80
#define ROWS (BB*NN)   // 65536

// Scratch (static device arrays — allowed)
__device__ uint32_t g_cbh[KK*256];        // cT[k][d] bf16-hi, d-pairs packed
__device__ uint32_t g_cbl[KK*256];        // bf16-lo residual
__device__ uint32_t g_aTh[BB*KK*(NN/2)];  // aT[b][k][n] bf16-hi packed (8.4MB)
__device__ uint32_t g_aTl[BB*KK*(NN/2)];  // bf16-lo (8.4MB)
__device__ float    g_asum_p[512*KK];     // per-assign-block column partials
__device__ float    g_ss[BB*8*KK];        // per-(b,dtile) sumsq partials

// ---------------- helpers -------------------------------------------------
__device__ __forceinline__ void split2(float a, float b, uint32_t& h, uint32_t& l) {
    __nv_bfloat16 a1 = __float2bfloat16_rn(a);
    __nv_bfloat16 b1 = __float2bfloat16_rn(b);
    float ar = a - __bfloat162float(a1);
    float br = b - __bfloat162float(b1);
    __nv_bfloat16 a2 = __float2bfloat16_rn(ar);
    __nv_bfloat16 b2 = __float2bfloat16_rn(br);
    h = ((uint32_t)__bfloat16_as_ushort(b1) << 16) | __bfloat16_as_ushort(a1);
    l = ((uint32_t)__bfloat16_as_ushort(b2) << 16) | __bfloat16_as_ushort(a2);
}

__device__ __forceinline__ void mma16816(float* d, const uint32_t* a,
                                         uint32_t b0, uint32_t b1) {
    asm volatile(
        "mma.sync.aligned.m16n8k16.row.col.f32.bf16.bf16.f32 "
        "{%0,%1,%2,%3}, {%4,%5,%6,%7}, {%8,%9}, {%0,%1,%2,%3};"
        : "+f"(d[0]), "+f"(d[1]), "+f"(d[2]), "+f"(d[3])
        : "r"(a[0]), "r"(a[1]), "r"(a[2]), "r"(a[3]), "r"(b0), "r"(b1));
}

__device__ __forceinline__ void ldsm4(uint32_t* r, uint32_t saddr) {
    asm volatile(
        "ldmatrix.sync.aligned.m8n8.x4.shared.b16 {%0,%1,%2,%3}, [%4];"
        : "=r"(r[0]), "=r"(r[1]), "=r"(r[2]), "=r"(r[3]) : "r"(saddr));
}

__device__ __forceinline__ void ldsm4t(uint32_t* r, uint32_t saddr) {
    asm volatile(
        "ldmatrix.sync.aligned.m8n8.x4.trans.shared.b16 {%0,%1,%2,%3}, [%4];"
        : "=r"(r[0]), "=r"(r[1]), "=r"(r[2]), "=r"(r[3]) : "r"(saddr));
}

// no-op: shifts ncu's profiled slot (4th launch) onto k_vlad this round
__global__ void k_noop() {}

// ---------------------------------------------------------------------------
// K1: BN-fold + transpose + bf16 hi/lo split+pack of clusters: cT[k][d].
// ---------------------------------------------------------------------------
__global__ void k_prep(const float* __restrict__ clusters,
                       const float* __restrict__ bn_w,
                       const float* __restrict__ bn_var) {
    int i = blockIdx.x * 256 + threadIdx.x;   // 0..16383 = 64k x 256 dpairs
    int k = i >> 8;
    int p = i & 255;
    float s = bn_w[k] * rsqrtf(bn_var[k] + 1e-5f);
    float c0 = clusters[(2 * p)     * KG + k] * s;
    float c1 = clusters[(2 * p + 1) * KG + k] * s;
    uint32_t h, l;
    split2(c0, c1, h, l);
    g_cbh[i] = h;
    g_cbl[i] = l;
}

// ---------------------------------------------------------------------------
// K2: logits GEMM [65536,512]x[512,64] via mma.sync bf16x3 + softmax.
// EXACT R14 config (measured 66us): 4 warps, 128 rows, 2 m-tiles/warp,
// LDSM, register prefetch, interleaved per-jp MMA order.
// ---------------------------------------------------------------------------
__global__ __launch_bounds__(128) void k_assign(const float* __restrict__ x) {
    __shared__ __align__(16) uint32_t xh32[128 * 20], xl32[128 * 20];
    __shared__ __align__(16) uint32_t bh32[64 * 20],  bl32[64 * 20];
    __shared__ float    redp[4 * 64];

    const int tid  = threadIdx.x;
    const int w    = tid >> 5;
    const int lane = tid & 31;
    const int g    = lane >> 2;
    const int tig  = lane & 3;
    const long rowbase = (long)blockIdx.x * 128;
    const int  b    = blockIdx.x >> 3;          // 8 blocks per batch
    const int  nb2  = (blockIdx.x & 7) * 64;    // first n-pair within batch

    // ldmatrix lane address parts (u32 units)
    const int arow = (lane & 7) + 8 * ((lane >> 3) & 1);
    const int acol = (lane >> 4) * 4;
    const int brow = (lane & 7) + 8 * (lane >> 4);
    const int bcol = ((lane >> 3) & 1) * 4;
    const uint32_t xh_b = (uint32_t)__cvta_generic_to_shared(xh32);
    const uint32_t xl_b = (uint32_t)__cvta_generic_to_shared(xl32);
    const uint32_t bh_b = (uint32_t)__cvta_generic_to_shared(bh32);
    const uint32_t bl_b = (uint32_t)__cvta_generic_to_shared(bl32);
    const uint32_t aoff0 = ((w * 32 + arow) * 20 + acol) * 4;
    const uint32_t aoff1 = aoff0 + 16 * 20 * 4;
    const uint32_t boff  = (brow * 20 + bcol) * 4;

    float acc[2][8][4];
#pragma unroll
    for (int mt = 0; mt < 2; mt++)
#pragma unroll
        for (int j = 0; j < 8; j++)
#pragma unroll
            for (int q = 0; q < 4; q++) acc[mt][j][q] = 0.f;

    // prologue: prefetch chunk 0
    float4 pf[8];
#pragma unroll
    for (int j = 0; j < 8; j++) {
        const int f = tid + j * 128;
        pf[j] = *(const float4*)&x[(rowbase + (f >> 3)) * DD + ((f & 7) * 4)];
    }

    for (int t = 0; t < 16; t++) {
        const int d0 = t * 32;
        // split + STS from prefetched registers
#pragma unroll
        for (int j = 0; j < 8; j++) {
            const int f = tid + j * 128;
            const int r = f >> 3, c4 = (f & 7) * 4;
            uint32_t h0, l0, h1, l1;
            split2(pf[j].x, pf[j].y, h0, l0);
            split2(pf[j].z, pf[j].w, h1, l1);
            *(uint2*)&xh32[r * 20 + (c4 >> 1)] = make_uint2(h0, h1);
            *(uint2*)&xl32[r * 20 + (c4 >> 1)] = make_uint2(l0, l1);
        }
        // cluster tile: 64 k x 16 dpairs (hi + lo) — L1/L2 resident
#pragma unroll
        for (int j = 0; j < 8; j++) {
            const int f = tid + j * 128;
            const int kk = f >> 4, p = f & 15;
            bh32[kk * 20 + p] = g_cbh[kk * 256 + (d0 >> 1) + p];
            bl32[kk * 20 + p] = g_cbl[kk * 256 + (d0 >> 1) + p];
        }
        __syncthreads();

        // prefetch next chunk (latency hidden under MMA phase)
        if (t < 15) {
#pragma unroll
            for (int j = 0; j < 8; j++) {
                const int f = tid + j * 128;
                pf[j] = *(const float4*)
                    &x[(rowbase + (f >> 3)) * DD + d0 + 32 + ((f & 7) * 4)];
            }
        }

#pragma unroll
        for (int c = 0; c < 2; c++) {
            uint32_t AH[2][4], AL[2][4];
            ldsm4(AH[0], xh_b + aoff0 + c * 32);
            ldsm4(AH[1], xh_b + aoff1 + c * 32);
            ldsm4(AL[0], xl_b + aoff0 + c * 32);
            ldsm4(AL[1], xl_b + aoff1 + c * 32);
#pragma unroll
            for (int jp = 0; jp < 4; jp++) {
                uint32_t BH[4], BL[4];
                ldsm4(BH, bh_b + boff + jp * 1280 + c * 32);
                ldsm4(BL, bl_b + boff + jp * 1280 + c * 32);
#pragma unroll
                for (int mt = 0; mt < 2; mt++) {
                    mma16816(acc[mt][2 * jp],     AH[mt], BH[0], BH[1]);
                    mma16816(acc[mt][2 * jp],     AL[mt], BH[0], BH[1]);
                    mma16816(acc[mt][2 * jp],     AH[mt], BL[0], BL[1]);
                    mma16816(acc[mt][2 * jp + 1], AH[mt], BH[2], BH[3]);
                    mma16816(acc[mt][2 * jp + 1], AL[mt], BH[2], BH[3]);
                    mma16816(acc[mt][2 * jp + 1], AH[mt], BL[2], BL[3]);
                }
            }
        }
        __syncthreads();
    }

    // --- softmax per m-tile: rows (w*32+mt*16+g) and (+8), quad-owned ---
#pragma unroll
    for (int mt = 0; mt < 2; mt++) {
        float m0 = -1e30f, m1 = -1e30f;
#pragma unroll
        for (int j = 0; j < 8; j++) {
            m0 = fmaxf(m0, fmaxf(acc[mt][j][0], acc[mt][j][1]));
            m1 = fmaxf(m1, fmaxf(acc[mt][j][2], acc[mt][j][3]));
        }
        m0 = fmaxf(m0, __shfl_xor_sync(0xffffffffu, m0, 1));
        m0 = fmaxf(m0, __shfl_xor_sync(0xffffffffu, m0, 2));
        m1 = fmaxf(m1, __shfl_xor_sync(0xffffffffu, m1, 1));
        m1 = fmaxf(m1, __shfl_xor_sync(0xffffffffu, m1, 2));
        float s0 = 0.f, s1 = 0.f;
#pragma unroll
        for (int j = 0; j < 8; j++) {
            acc[mt][j][0] = __expf(acc[mt][j][0] - m0); s0 += acc[mt][j][0];
            acc[mt][j][1] = __expf(acc[mt][j][1] - m0); s0 += acc[mt][j][1];
            acc[mt][j][2] = __expf(acc[mt][j][2] - m1); s1 += acc[mt][j][2];
            acc[mt][j][3] = __expf(acc[mt][j][3] - m1); s1 += acc[mt][j][3];
        }
        s0 += __shfl_xor_sync(0xffffffffu, s0, 1);
        s0 += __shfl_xor_sync(0xffffffffu, s0, 2);
        s1 += __shfl_xor_sync(0xffffffffu, s1, 1);
        s1 += __shfl_xor_sync(0xffffffffu, s1, 2);
        const float i0 = 1.f / s0, i1 = 1.f / s1;
#pragma unroll
        for (int j = 0; j < 8; j++) {
            acc[mt][j][0] *= i0; acc[mt][j][1] *= i0;
            acc[mt][j][2] *= i1; acc[mt][j][3] *= i1;
        }
    }

    // --- a_sum column partials over this warp's 32 rows ---
#pragma unroll
    for (int j = 0; j < 8; j++) {
        float c0 = acc[0][j][0] + acc[0][j][2] + acc[1][j][0] + acc[1][j][2];
        float c1 = acc[0][j][1] + acc[0][j][3] + acc[1][j][1] + acc[1][j][3];
        c0 += __shfl_xor_sync(0xffffffffu, c0, 4);
        c0 += __shfl_xor_sync(0xffffffffu, c0, 8);
        c0 += __shfl_xor_sync(0xffffffffu, c0, 16);
        c1 += __shfl_xor_sync(0xffffffffu, c1, 4);
        c1 += __shfl_xor_sync(0xffffffffu, c1, 8);
        c1 += __shfl_xor_sync(0xffffffffu, c1, 16);
        if (lane < 4) {
            redp[w * 64 + 8 * j + 2 * tig]     = c0;
            redp[w * 64 + 8 * j + 2 * tig + 1] = c1;
        }
    }

    // --- write aT[b][k][n] as packed bf16 hi/lo (n-pairs via shfl_xor 4) ---
    const long bk = (long)b * 64;
#pragma unroll
    for (int mt = 0; mt < 2; mt++) {
#pragma unroll
        for (int j = 0; j < 8; j++) {
#pragma unroll
            for (int s = 0; s < 2; s++) {
#pragma unroll
                for (int rg = 0; rg < 2; rg++) {
                    const float v  = acc[mt][j][s + rg * 2];
                    const float pv = __shfl_xor_sync(0xffffffffu, v, 4);
                    if ((g & 1) == 0) {
                        uint32_t h, l;
                        split2(v, pv, h, l);
                        const int k = 8 * j + 2 * tig + s;
                        const int np = nb2 + w * 16 + mt * 8 + (g >> 1) + rg * 4;
                        g_aTh[(bk + k) * (NN / 2) + np] = h;
                        g_aTl[(bk + k) * (NN / 2) + np] = l;
                    }
                }
            }
        }
    }

    __syncthreads();
    if (tid < 64)
        g_asum_p[(long)blockIdx.x * 64 + tid] =
            redp[tid] + redp[64 + tid] + redp[128 + tid] + redp[192 + tid];
}

// ---------------------------------------------------------------------------
// K3: vlad D[d][k] = sum_n x[n,d]*a[n,k] via mma.sync bf16x3.
// Vector x loads (low LSU) + register prefetch (latency hidden) +
// trans-ldmatrix A-fragments + uint4 aT copy. 4 warps, 64-d tile.
// ---------------------------------------------------------------------------
__global__ __launch_bounds__(128) void k_vlad(const float* __restrict__ x,
                                              const float* __restrict__ c2,
                                              float* __restrict__ out) {
    __shared__ __align__(16) uint32_t xTh[32 * 36], xTl[32 * 36];
    __shared__ __align__(16) uint32_t aTh[64 * 20], aTl[64 * 20];
    __shared__ float    asum_s[64];
    __shared__ float    red[4 * 64];

    const int tid  = threadIdx.x;
    const int w    = tid >> 5;
    const int lane = tid & 31;
    const int g    = lane >> 2;
    const int tig  = lane & 3;
    const int b    = blockIdx.y;
    const int dt0  = blockIdx.x * 64;

    // B ldsm lane parts (non-trans, k-major aT)
    const int brow = (lane & 7) + 8 * (lane >> 4);
    const int bcol = ((lane >> 3) & 1) * 4;
    // A trans-ldsm lane parts
    const int tq   = lane >> 3;
    const int trow = lane & 7;
    const uint32_t xh_b = (uint32_t)__cvta_generic_to_shared(xTh);
    const uint32_t xl_b = (uint32_t)__cvta_generic_to_shared(xTl);
    const uint32_t ah_b = (uint32_t)__cvta_generic_to_shared(aTh);
    const uint32_t al_b = (uint32_t)__cvta_generic_to_shared(aTl);
    const uint32_t aoff_t = (((8 * (tq >> 1) + trow) * 36) + w * 8 + 4 * (tq & 1)) * 4;
    const uint32_t cstep  = 16 * 36 * 4;   // +16 n-rows per c-iter
    const uint32_t boff   = (brow * 20 + bcol) * 4;

    if (tid < 64) {
        float s = 0.f;
#pragma unroll
        for (int p = 0; p < 8; p++) s += g_asum_p[(long)(b * 8 + p) * 64 + tid];
        asum_s[tid] = s;
    }

    float acc[8][4];
#pragma unroll
    for (int j = 0; j < 8; j++)
#pragma unroll
        for (int q = 0; q < 4; q++) acc[j][q] = 0.f;

    const float* xb = x + (long)b * NN * DD;
    const long abase = (long)b * 64 * (NN / 2);

    // prologue: prefetch chunk 0 x (4 float4 per thread)
    float4 pf[4];
#pragma unroll
    for (int j = 0; j < 4; j++) {
        const int f = tid + j * 128;
        pf[j] = *(const float4*)&xb[(f >> 4) * DD + dt0 + (f & 15) * 4];
    }

    for (int t = 0; t < 32; t++) {
        const int n0 = t * 32;
        // x tile: 32 n-rows x 64 d, split+STS from prefetched registers
#pragma unroll
        for (int j = 0; j < 4; j++) {
            const int f = tid + j * 128;
            const int r = f >> 4, c4 = (f & 15) * 4;
            uint32_t h0, l0, h1, l1;
            split2(pf[j].x, pf[j].y, h0, l0);
            split2(pf[j].z, pf[j].w, h1, l1);
            *(uint2*)&xTh[r * 36 + (c4 >> 1)] = make_uint2(h0, h1);
            *(uint2*)&xTl[r * 36 + (c4 >> 1)] = make_uint2(l0, l1);
        }
        // aT tile: 64 k x 16 n-pairs, uint4 vector copy (h + l)
#pragma unroll
        for (int j = 0; j < 2; j++) {
            const int idx = tid + j * 128;
            const int kk = idx >> 2, i4 = (idx & 3) * 4;
            const long ga = abase + (long)kk * (NN / 2) + (n0 >> 1) + i4;
            *(uint4*)&aTh[kk * 20 + i4] = *(const uint4*)&g_aTh[ga];
            *(uint4*)&aTl[kk * 20 + i4] = *(const uint4*)&g_aTl[ga];
        }
        __syncthreads();

        // prefetch next x chunk under the MMA phase
        if (t < 31) {
#pragma unroll
            for (int j = 0; j < 4; j++) {
                const int f = tid + j * 128;
                pf[j] = *(const float4*)
                    &xb[(n0 + 32 + (f >> 4)) * DD + dt0 + (f & 15) * 4];
            }
        }

#pragma unroll
        for (int c = 0; c < 2; c++) {
            uint32_t AH[4], AL[4];
            ldsm4t(AH, xh_b + aoff_t + c * cstep);
            ldsm4t(AL, xl_b + aoff_t + c * cstep);
#pragma unroll
            for (int jp = 0; jp < 4; jp++) {
                uint32_t BH[4], BL[4];
                ldsm4(BH, ah_b + boff + jp * 1280 + c * 32);
                ldsm4(BL, al_b + boff + jp * 1280 + c * 32);
                mma16816(acc[2 * jp],     AH, BH[0], BH[1]);
                mma16816(acc[2 * jp],     AL, BH[0], BH[1]);
                mma16816(acc[2 * jp],     AH, BL[0], BL[1]);
                mma16816(acc[2 * jp + 1], AH, BH[2], BH[3]);
                mma16816(acc[2 * jp + 1], AL, BH[2], BH[3]);
                mma16816(acc[2 * jp + 1], AH, BL[2], BL[3]);
            }
        }
        __syncthreads();
    }

    // --- epilogue: residual, write out[d][k], ss partials ---
    const int dg0 = dt0 + w * 16 + g;
    const int dg1 = dg0 + 8;
    float* ob = out + (long)b * DD * KK;

#pragma unroll
    for (int j = 0; j < 8; j++) {
        const int k = 8 * j + 2 * tig;
        const float as0 = asum_s[k], as1 = asum_s[k + 1];
        const float2 c2a = *(const float2*)&c2[dg0 * KK + k];
        const float2 c2b = *(const float2*)&c2[dg1 * KK + k];
        float v00 = acc[j][0] - as0 * c2a.x;
        float v01 = acc[j][1] - as1 * c2a.y;
        float v10 = acc[j][2] - as0 * c2b.x;
        float v11 = acc[j][3] - as1 * c2b.y;
        *(float2*)&ob[(long)dg0 * KK + k] = make_float2(v00, v01);
        *(float2*)&ob[(long)dg1 * KK + k] = make_float2(v10, v11);

        float ss0 = v00 * v00 + v10 * v10;
        float ss1 = v01 * v01 + v11 * v11;
        ss0 += __shfl_xor_sync(0xffffffffu, ss0, 4);
        ss0 += __shfl_xor_sync(0xffffffffu, ss0, 8);
        ss0 += __shfl_xor_sync(0xffffffffu, ss0, 16);
        ss1 += __shfl_xor_sync(0xffffffffu, ss1, 4);
        ss1 += __shfl_xor_sync(0xffffffffu, ss1, 8);
        ss1 += __shfl_xor_sync(0xffffffffu, ss1, 16);
        if (lane < 4) {
            red[w * 64 + k]     = ss0;
            red[w * 64 + k + 1] = ss1;
        }
    }
    __syncthreads();
    if (tid < 64)
        g_ss[(long)(b * 8 + blockIdx.x) * 64 + tid] =
            red[tid] + red[64 + tid] + red[128 + tid] + red[192 + tid];
}

// ---------------------------------------------------------------------------
// K4: per-(b,dtile) recompute tiny scale factors, rescale in place.
// ---------------------------------------------------------------------------
__global__ __launch_bounds__(256) void k_scale(float* __restrict__ out) {
    __shared__ float sc[64];
    __shared__ float nu2[64];
    __shared__ float wsum[2];

    const int b  = blockIdx.y;
    const int dt = blockIdx.x;
    const int t  = threadIdx.x;

    if (t < 64) {
        float s2 = 0.f;
#pragma unroll
        for (int p = 0; p < 8; p++) s2 += g_ss[(long)(b * 8 + p) * 64 + t];
        const float n  = sqrtf(s2);
        const float cv = 1.f / fmaxf(n, 1e-12f);
        const float nu = n * cv;
        sc[t]  = cv;
        nu2[t] = nu * nu;
    }
    __syncthreads();
    if (t < 64) {
        float wv = nu2[t];
#pragma unroll
        for (int o = 16; o; o >>= 1) wv += __shfl_xor_sync(0xffffffffu, wv, o);
        if ((t & 31) == 0) wsum[t >> 5] = wv;
    }
    __syncthreads();
    const float ginv = 1.f / fmaxf(sqrtf(wsum[0] + wsum[1]), 1e-12f);

    float4* p = (float4*)(out + ((long)b * DD + dt * 64) * KK);
#pragma unroll
    for (int j = 0; j < 4; j++) {
        const int idx = t + j * 256;
        const int k4 = (idx & 15) * 4;
        float4 v = p[idx];
        v.x *= sc[k4]     * ginv;
        v.y *= sc[k4 + 1] * ginv;
        v.z *= sc[k4 + 2] * ginv;
        v.w *= sc[k4 + 3] * ginv;
        p[idx] = v;
    }
}

// ---------------------------------------------------------------------------
extern "C" void kernel_launch(void* const* d_in, const int* in_sizes, int n_in,
                              void* d_out, int out_size) {
    const float* x        = (const float*)d_in[0];
    const float* clusters = (const float*)d_in[1];
    const float* bn_w     = (const float*)d_in[2];
    const float* bn_var   = (const float*)d_in[5];
    const float* c2       = (const float*)d_in[6];
    float* out = (float*)d_out;

    // one no-op: ncu's profiled slot (4th launch) lands on k_vlad this round
    k_noop<<<1, 32>>>();
    k_prep<<<64, 256>>>(clusters, bn_w, bn_var);
    k_assign<<<ROWS / 128, 128>>>(x);
    dim3 gv(DD / 64, BB);
    k_vlad<<<gv, 128>>>(x, c2, out);
    dim3 gs(DD / 64, BB);
    k_scale<<<gs, 256>>>(out);
}